// round 13
// baseline (speedup 1.0000x reference)
#include <cuda_runtime.h>
#include <cuda_fp16.h>
#include <cstdint>
#include <math.h>

#define B_ 8
#define N_ 1024
#define D_ 512
#define H_ 4

// ---------------------------------------------------------------------------
// Scratch (device globals; no allocation allowed)
// ---------------------------------------------------------------------------
__device__ __align__(16) __half g_xs_h[(size_t)B_ * N_ * D_];
__device__ __align__(16) __half g_xs_r[(size_t)B_ * N_ * D_];
__device__ __align__(16) __half g_xt_h[(size_t)B_ * D_ * N_];
__device__ __align__(16) __half g_Wt_h[(size_t)H_ * D_ * D_];
__device__ __align__(16) __half g_Wt_r[(size_t)H_ * D_ * D_];
__device__ __align__(16) __half g_Y_h[(size_t)B_ * H_ * N_ * D_];
__device__ __align__(16) __half g_Y_r[(size_t)B_ * H_ * N_ * D_];
__device__ __align__(16) float  g_S  [(size_t)B_ * H_ * N_ * N_];
__device__ __align__(16) __half g_P_h[(size_t)B_ * H_ * N_ * N_];

// ---------------------------------------------------------------------------
// helpers (portable sm_80+ PTX)
// ---------------------------------------------------------------------------
__device__ __forceinline__ uint32_t smem_u32(const void* p) {
    uint32_t a;
    asm("{ .reg .u64 t; cvta.to.shared.u64 t, %1; cvt.u32.u64 %0, t; }"
        : "=r"(a) : "l"(p));
    return a;
}

#define CP16(dst, src) \
    asm volatile("cp.async.cg.shared.global [%0], [%1], 16;" \
                 :: "r"(dst), "l"(src))
#define CP_COMMIT() asm volatile("cp.async.commit_group;" ::: "memory")
#define CP_WAIT1()  asm volatile("cp.async.wait_group 1;"  ::: "memory")

#define LDSM4(r, a)                                                           \
    asm volatile("ldmatrix.sync.aligned.m8n8.x4.shared.b16 {%0,%1,%2,%3}, [%4];" \
                 : "=r"((r)[0]), "=r"((r)[1]), "=r"((r)[2]), "=r"((r)[3])     \
                 : "r"(a))

#define MMA(c, a, b)                                                          \
    asm volatile("mma.sync.aligned.m16n8k16.row.col.f32.f16.f16.f32 "         \
                 "{%0,%1,%2,%3},{%4,%5,%6,%7},{%8,%9},{%0,%1,%2,%3};"         \
                 : "+f"((c)[0]), "+f"((c)[1]), "+f"((c)[2]), "+f"((c)[3])     \
                 : "r"((a)[0]), "r"((a)[1]), "r"((a)[2]), "r"((a)[3]),        \
                   "r"((b)[0]), "r"((b)[1]))

// swizzle within a 128B row
#define SWZC(row, colB) ((uint32_t)(colB) ^ (((uint32_t)(row) & 7u) << 4))

// smem stages: 32KB each, 3 stages.
// TERMS=3: K-chunk 32, row = [hi k0..31 | lo k0..31] (128B)
// TERMS=1: K-chunk 64, row = [hi k0..63] (128B)
#define AT_B   (128 * 128)           // 16384
#define BT_B   (128 * 128)           // 16384
#define STG_B  (AT_B + BT_B)         // 32768
#define OFF_B  AT_B
#define NSTG   3
#define GSMEM  (NSTG * STG_B)        // 98304

// ---------------------------------------------------------------------------
// Split-fp16 mma.sync GEMM (NT):
//   C[m,n] = alpha * sum_seg sum_k A_seg[m,k] B[n,k]
// TERMS 3: ah*bh + ah*bl + al*bh  (A = Ah+Ar, B = Bh+Br)
// TERMS 1: ah*bh                  (pure fp16)
// CTA tile 128x128, 8 warps (2m x 4n), warp tile 64x32,
// 3-stage cp.async ring, 2 CTAs/SM.
// Chunks-per-segment is ALWAYS 16 (K1/K2: 512/32, K4: 1024/64) -> shift/mask.
// EPI 0: fp32 C.  EPI 1: (h, r) fp16 pair.
// ---------------------------------------------------------------------------
template <int EPI, int TERMS>
__global__ __launch_bounds__(256, 2) void gemm_mma(
    const __half* __restrict__ Ahi, const __half* __restrict__ Alo,
    int ldA, size_t aBatch, int aDiv, int aMod, size_t aSeg, int nSeg,
    const __half* __restrict__ Bhi, const __half* __restrict__ Blo,
    int ldB, size_t bBatch, int bDiv, int bMod,
    int K,
    float* __restrict__ Cf,
    __half* __restrict__ Chi, __half* __restrict__ Clo,
    int ldC, size_t cBatch, float alpha)
{
    extern __shared__ char smem[];
    const uint32_t sb = smem_u32(smem);
    const int tid = threadIdx.x;
    const int wid = tid >> 5, lane = tid & 31;
    const int wm = (wid >> 2) * 64;     // 2 m-groups
    const int wn = (wid & 3) * 32;      // 4 n-groups
    const int z = blockIdx.z;
    const int m0 = blockIdx.y * 128;
    const int n0 = blockIdx.x * 128;

    Ahi += (size_t)((z / aDiv) % aMod) * aBatch;
    if (TERMS == 3) Alo += (size_t)((z / aDiv) % aMod) * aBatch;
    Bhi += (size_t)((z / bDiv) % bMod) * bBatch;
    if (TERMS == 3) Blo += (size_t)((z / bDiv) % bMod) * bBatch;

    constexpr int KC  = (TERMS == 3) ? 32 : 64;   // K per chunk
    constexpr int NKS = KC / 16;                  // k16 steps per chunk
    constexpr int CPS = 16;                       // chunks per segment (all uses)
    const int total = nSeg * CPS;

// seg = ch>>4, k0 = (ch&15)*KC  -- shift/mask only, one offset add per CP16
#define LOAD_CHUNK(ch, stg) do {                                              \
        const int k0_ = ((ch) & 15) * KC;                                     \
        const size_t segOff_ = (size_t)((ch) >> 4) * aSeg + k0_;              \
        const uint32_t bb_ = sb + (stg) * STG_B;                              \
        if (TERMS == 3) {                                                     \
            _Pragma("unroll")                                                 \
            for (int it = 0; it < 4; it++) {   /* A: 128 rows x 8 pieces */   \
                const int idx = tid + it * 256;                               \
                const int row = idx >> 3;                                     \
                const int p = idx & 7;                                        \
                const __half* src = (p < 4) ? Ahi : Alo;                      \
                const uint32_t d = row * 128 + SWZC(row, p * 16);             \
                CP16(bb_ + d, (const char*)(src + (size_t)(m0 + row) * ldA    \
                                            + segOff_ + (p & 3) * 8));        \
            }                                                                 \
            _Pragma("unroll")                                                 \
            for (int it = 0; it < 4; it++) {  /* B: 128 rows x 8 pieces */    \
                const int idx = tid + it * 256;                               \
                const int row = idx >> 3;                                     \
                const int p = idx & 7;                                        \
                const __half* src = (p < 4) ? Bhi : Blo;                      \
                const uint32_t d = OFF_B + row * 128 + SWZC(row, p * 16);     \
                CP16(bb_ + d, (const char*)(src + (size_t)(n0 + row) * ldB    \
                                            + k0_ + (p & 3) * 8));            \
            }                                                                 \
        } else {            /* hi only, 64 k per row: 128 rows x 8 pieces */  \
            _Pragma("unroll")                                                 \
            for (int it = 0; it < 4; it++) {                                  \
                const int idx = tid + it * 256;                               \
                const int row = idx >> 3;                                     \
                const int p = idx & 7;                                        \
                const uint32_t d = row * 128 + SWZC(row, p * 16);             \
                CP16(bb_ + d, (const char*)(Ahi + (size_t)(m0 + row) * ldA    \
                                            + segOff_ + p * 8));              \
            }                                                                 \
            _Pragma("unroll")                                                 \
            for (int it = 0; it < 4; it++) {                                  \
                const int idx = tid + it * 256;                               \
                const int row = idx >> 3;                                     \
                const int p = idx & 7;                                        \
                const uint32_t d = OFF_B + row * 128 + SWZC(row, p * 16);     \
                CP16(bb_ + d, (const char*)(Bhi + (size_t)(n0 + row) * ldB    \
                                            + k0_ + p * 8));                  \
            }                                                                 \
        }                                                                     \
    } while (0)

    float acc[4][4][4];
#pragma unroll
    for (int i = 0; i < 4; i++)
#pragma unroll
        for (int j = 0; j < 4; j++)
#pragma unroll
            for (int r = 0; r < 4; r++) acc[i][j][r] = 0.f;

    LOAD_CHUNK(0, 0); CP_COMMIT();
    LOAD_CHUNK(1, 1); CP_COMMIT();

    // per-lane LDSM geometry
    const int aRow = lane & 15;                              // A: 16x16 frags
    const int aCol0 = lane & 16;                             // 0 / 16 bytes
    const int bRow0 = (lane & 7) + ((lane >> 4) & 1) * 8;    // B: 16-row pair
    const int bCol0 = ((lane >> 3) & 1) * 16;

    int stg = 0;                // stage holding chunk `ch`
    for (int ch = 0; ch < total; ch++) {
        CP_WAIT1();
        __syncthreads();

        const uint32_t bb = sb + stg * STG_B;

#pragma unroll
        for (int ks = 0; ks < NKS; ks++) {
            const int colH = ks * 32;
            // --- fragment loads first (B frags + A tile 0) ---
            uint32_t bh[4][2], bl[4][2];
#pragma unroll
            for (int jj = 0; jj < 2; jj++) {
                const int row = wn + jj * 16 + bRow0;
                const uint32_t rb = bb + OFF_B + row * 128;
                LDSM4(&bh[jj * 2][0], rb + SWZC(row, colH + bCol0));
                if (TERMS == 3) LDSM4(&bl[jj * 2][0], rb + SWZC(row, colH + bCol0 + 64));
            }
            uint32_t ahc[4], alc[4], ahn[4], aln[4];
            {
                const int row = wm + aRow;
                const uint32_t ra = bb + row * 128;
                LDSM4(ahc, ra + SWZC(row, colH + aCol0));
                if (TERMS == 3) LDSM4(alc, ra + SWZC(row, colH + aCol0 + 64));
            }
            // --- overlap next chunk's cp.async issue with LDSM latency ---
            if (ks == 0) {
                int nstg = stg + 2; if (nstg >= NSTG) nstg -= NSTG;
                if (ch + 2 < total) { LOAD_CHUNK(ch + 2, nstg); }
                CP_COMMIT();
            }
            // --- MMAs, streaming A tiles one ahead ---
#pragma unroll
            for (int i = 0; i < 4; i++) {
                if (i < 3) {
                    const int row = wm + (i + 1) * 16 + aRow;
                    const uint32_t ra = bb + row * 128;
                    LDSM4(ahn, ra + SWZC(row, colH + aCol0));
                    if (TERMS == 3) LDSM4(aln, ra + SWZC(row, colH + aCol0 + 64));
                }
#pragma unroll
                for (int j = 0; j < 4; j++) MMA(acc[i][j], ahc, bh[j]);
                if (TERMS == 3) {
#pragma unroll
                    for (int j = 0; j < 4; j++) MMA(acc[i][j], ahc, bl[j]);
#pragma unroll
                    for (int j = 0; j < 4; j++) MMA(acc[i][j], alc, bh[j]);
                }
#pragma unroll
                for (int r = 0; r < 4; r++) {
                    ahc[r] = ahn[r];
                    if (TERMS == 3) alc[r] = aln[r];
                }
            }
        }
        stg = stg + 1; if (stg >= NSTG) stg = 0;
    }
#undef LOAD_CHUNK

    // ---- epilogue (vectorized stores) ----
    const int cr = lane >> 2, cc = (lane & 3) * 2;
#pragma unroll
    for (int i = 0; i < 4; i++) {
        const int r0 = m0 + wm + i * 16 + cr;
#pragma unroll
        for (int j = 0; j < 4; j++) {
            const int col = n0 + wn + j * 8 + cc;
            const size_t o0 = (size_t)z * cBatch + (size_t)r0 * ldC + col;
            const size_t o1 = o0 + (size_t)8 * ldC;
            float v0 = acc[i][j][0] * alpha, v1 = acc[i][j][1] * alpha;
            float v2 = acc[i][j][2] * alpha, v3 = acc[i][j][3] * alpha;
            if (EPI == 0) {
                *(float2*)&Cf[o0] = make_float2(v0, v1);
                *(float2*)&Cf[o1] = make_float2(v2, v3);
            } else {
                float h0 = __half2float(__float2half_rn(v0));
                float h1 = __half2float(__float2half_rn(v1));
                float h2 = __half2float(__float2half_rn(v2));
                float h3 = __half2float(__float2half_rn(v3));
                *(__half2*)&Chi[o0] = __floats2half2_rn(v0, v1);
                *(__half2*)&Chi[o1] = __floats2half2_rn(v2, v3);
                *(__half2*)&Clo[o0] = __floats2half2_rn(v0 - h0, v1 - h1);
                *(__half2*)&Clo[o1] = __floats2half2_rn(v2 - h2, v3 - h3);
            }
        }
    }
}

// ---------------------------------------------------------------------------
// Split x -> xs (h/r, [B,N,D]) and xt (h only, [B,D,N])
// ---------------------------------------------------------------------------
__global__ __launch_bounds__(256) void split_x_kernel(const float* __restrict__ x) {
    __shared__ float t[32][33];
    const int b = blockIdx.z;
    const int d0 = blockIdx.x * 32, n0 = blockIdx.y * 32;
    const int tx = threadIdx.x & 31, ty = threadIdx.x >> 5;

    for (int i = ty; i < 32; i += 8)
        t[i][tx] = x[(size_t)b * N_ * D_ + (size_t)(n0 + i) * D_ + d0 + tx];
    __syncthreads();

    for (int i = ty; i < 32; i += 8) {
        float v = t[i][tx];
        __half h = __float2half_rn(v);
        size_t o = (size_t)b * N_ * D_ + (size_t)(n0 + i) * D_ + d0 + tx;
        g_xs_h[o] = h; g_xs_r[o] = __float2half_rn(v - __half2float(h));
    }
    for (int i = ty; i < 32; i += 8) {
        float v = t[tx][i];
        size_t o = (size_t)b * D_ * N_ + (size_t)(d0 + i) * N_ + n0 + tx;
        g_xt_h[o] = __float2half_rn(v);
    }
}

__global__ __launch_bounds__(256) void split_w_kernel(const float* __restrict__ W) {
    __shared__ float t[32][33];
    const int h = blockIdx.z;
    const int e0 = blockIdx.x * 32, d0 = blockIdx.y * 32;
    const int tx = threadIdx.x & 31, ty = threadIdx.x >> 5;

    for (int i = ty; i < 32; i += 8)
        t[i][tx] = W[(size_t)h * D_ * D_ + (size_t)(d0 + i) * D_ + e0 + tx];
    __syncthreads();

    for (int i = ty; i < 32; i += 8) {
        float v = t[tx][i];   // W[d0+tx][e0+i]
        __half hh = __float2half_rn(v);
        size_t o = (size_t)h * D_ * D_ + (size_t)(e0 + i) * D_ + d0 + tx;
        g_Wt_h[o] = hh; g_Wt_r[o] = __float2half_rn(v - __half2float(hh));
    }
}

// ---------------------------------------------------------------------------
// Softmax over rows of g_S; writes fp16 P (hi only)
// ---------------------------------------------------------------------------
__global__ __launch_bounds__(256) void softmax_split_kernel() {
    const size_t row = blockIdx.x;
    const float* p = g_S + row * N_;
    const int tid = threadIdx.x;
    __shared__ float red[8];

    float4 v = *(const float4*)&p[tid * 4];
    float m = fmaxf(fmaxf(v.x, v.y), fmaxf(v.z, v.w));
#pragma unroll
    for (int o = 16; o; o >>= 1) m = fmaxf(m, __shfl_xor_sync(0xFFFFFFFFu, m, o));
    if ((tid & 31) == 0) red[tid >> 5] = m;
    __syncthreads();
    float bm = red[0];
#pragma unroll
    for (int i = 1; i < 8; i++) bm = fmaxf(bm, red[i]);
    __syncthreads();

    v.x = __expf(v.x - bm); v.y = __expf(v.y - bm);
    v.z = __expf(v.z - bm); v.w = __expf(v.w - bm);
    float s = v.x + v.y + v.z + v.w;
#pragma unroll
    for (int o = 16; o; o >>= 1) s += __shfl_xor_sync(0xFFFFFFFFu, s, o);
    if ((tid & 31) == 0) red[tid >> 5] = s;
    __syncthreads();
    float bs = 0.f;
#pragma unroll
    for (int i = 0; i < 8; i++) bs += red[i];
    float inv = 1.0f / bs;

    __half2* dst = (__half2*)&g_P_h[row * N_ + tid * 4];
    dst[0] = __floats2half2_rn(v.x * inv, v.y * inv);
    dst[1] = __floats2half2_rn(v.z * inv, v.w * inv);
}

// ---------------------------------------------------------------------------
extern "C" void kernel_launch(void* const* d_in, const int* in_sizes, int n_in,
                              void* d_out, int out_size) {
    const float* x = (const float*)d_in[0];   // [8,1024,512]
    const float* W = (const float*)d_in[1];   // [4,512,512]
    float* out = (float*)d_out;               // [8,1024,512]

    cudaFuncSetAttribute(gemm_mma<0, 3>, cudaFuncAttributeMaxDynamicSharedMemorySize, GSMEM);
    cudaFuncSetAttribute(gemm_mma<1, 3>, cudaFuncAttributeMaxDynamicSharedMemorySize, GSMEM);
    cudaFuncSetAttribute(gemm_mma<0, 1>, cudaFuncAttributeMaxDynamicSharedMemorySize, GSMEM);

    __half *xs_h, *xs_r, *xt_h, *Wt_h, *Wt_r, *Y_h, *Y_r, *P_h;
    float* Sf;
    cudaGetSymbolAddress((void**)&xs_h, g_xs_h);
    cudaGetSymbolAddress((void**)&xs_r, g_xs_r);
    cudaGetSymbolAddress((void**)&xt_h, g_xt_h);
    cudaGetSymbolAddress((void**)&Wt_h, g_Wt_h);
    cudaGetSymbolAddress((void**)&Wt_r, g_Wt_r);
    cudaGetSymbolAddress((void**)&Y_h, g_Y_h);
    cudaGetSymbolAddress((void**)&Y_r, g_Y_r);
    cudaGetSymbolAddress((void**)&P_h, g_P_h);
    cudaGetSymbolAddress((void**)&Sf, g_S);

    const float SCALE = 0.04419417382415922f;   // 512^-0.5

    split_x_kernel<<<dim3(D_ / 32, N_ / 32, B_), 256>>>(x);
    split_w_kernel<<<dim3(D_ / 32, D_ / 32, H_), 256>>>(W);

    // K1: Y[b,h] = xs[b] @ Wt[h]^T  (3-term) -> fp16 h/r Y
    gemm_mma<1, 3><<<dim3(D_ / 128, N_ / 128, B_ * H_), 256, GSMEM>>>(
        xs_h, xs_r, D_, (size_t)N_ * D_, 4, 8, 0, 1,
        Wt_h, Wt_r, D_, (size_t)D_ * D_, 1, 4,
        D_,
        nullptr, Y_h, Y_r, D_, (size_t)N_ * D_, 1.0f);

    // K2: S[b,h] = scale * Y[b,h] @ xs[b]^T  (3-term) -> fp32
    gemm_mma<0, 3><<<dim3(N_ / 128, N_ / 128, B_ * H_), 256, GSMEM>>>(
        Y_h, Y_r, D_, (size_t)N_ * D_, 1, 32, 0, 1,
        xs_h, xs_r, D_, (size_t)N_ * D_, 4, 8,
        D_,
        Sf, nullptr, nullptr, N_, (size_t)N_ * N_, SCALE);

    softmax_split_kernel<<<B_ * H_ * N_, 256>>>();

    // K4: out[b] = 0.25 * sum_h P_h[b,h] @ xt_h[b]^T  (1-term fp16,
    //     4 head-segments accumulated in registers, direct out write)
    gemm_mma<0, 1><<<dim3(D_ / 128, N_ / 128, B_), 256, GSMEM>>>(
        P_h, nullptr, N_, (size_t)H_ * N_ * N_, 1, 8, (size_t)N_ * N_, H_,
        xt_h, nullptr, N_, (size_t)D_ * N_, 1, 8,
        N_,
        out, nullptr, nullptr, D_, (size_t)N_ * D_, 0.25f);
}

// round 14
// speedup vs baseline: 1.5360x; 1.5360x over previous
#include <cuda_runtime.h>
#include <cuda_fp16.h>
#include <cstdint>
#include <math.h>

#define B_ 8
#define N_ 1024
#define D_ 512
#define H_ 4

// ---------------------------------------------------------------------------
// Scratch (device globals; no allocation allowed)
// ---------------------------------------------------------------------------
__device__ __align__(16) __half g_xs_h[(size_t)B_ * N_ * D_];
__device__ __align__(16) __half g_xs_r[(size_t)B_ * N_ * D_];
__device__ __align__(16) __half g_xt_h[(size_t)B_ * D_ * N_];
__device__ __align__(16) __half g_Wt_h[(size_t)H_ * D_ * D_];
__device__ __align__(16) __half g_Wt_r[(size_t)H_ * D_ * D_];
__device__ __align__(16) __half g_Y_h[(size_t)B_ * H_ * N_ * D_];
__device__ __align__(16) __half g_Y_r[(size_t)B_ * H_ * N_ * D_];
__device__ __align__(16) float  g_S  [(size_t)B_ * H_ * N_ * N_];
__device__ __align__(16) __half g_P_h[(size_t)B_ * H_ * N_ * N_];

// ---------------------------------------------------------------------------
// helpers (portable sm_80+ PTX)
// ---------------------------------------------------------------------------
__device__ __forceinline__ uint32_t smem_u32(const void* p) {
    uint32_t a;
    asm("{ .reg .u64 t; cvta.to.shared.u64 t, %1; cvt.u32.u64 %0, t; }"
        : "=r"(a) : "l"(p));
    return a;
}

#define CP16(dst, src) \
    asm volatile("cp.async.cg.shared.global [%0], [%1], 16;" \
                 :: "r"(dst), "l"(src))
#define CP_COMMIT() asm volatile("cp.async.commit_group;" ::: "memory")
#define CP_WAIT1()  asm volatile("cp.async.wait_group 1;"  ::: "memory")

#define LDSM4(r, a)                                                           \
    asm volatile("ldmatrix.sync.aligned.m8n8.x4.shared.b16 {%0,%1,%2,%3}, [%4];" \
                 : "=r"((r)[0]), "=r"((r)[1]), "=r"((r)[2]), "=r"((r)[3])     \
                 : "r"(a))

#define MMA(c, a, b)                                                          \
    asm volatile("mma.sync.aligned.m16n8k16.row.col.f32.f16.f16.f32 "         \
                 "{%0,%1,%2,%3},{%4,%5,%6,%7},{%8,%9},{%0,%1,%2,%3};"         \
                 : "+f"((c)[0]), "+f"((c)[1]), "+f"((c)[2]), "+f"((c)[3])     \
                 : "r"((a)[0]), "r"((a)[1]), "r"((a)[2]), "r"((a)[3]),        \
                   "r"((b)[0]), "r"((b)[1]))

// swizzle within a 128B row
#define SWZC(row, colB) ((uint32_t)(colB) ^ (((uint32_t)(row) & 7u) << 4))

// smem stages: 32KB each, 3 stages.
// TERMS=3: K-chunk 32, row = [hi k0..31 | lo k0..31] (128B)
// TERMS=1: K-chunk 64, row = [hi k0..63] (128B)
#define AT_B   (128 * 128)           // 16384
#define BT_B   (128 * 128)           // 16384
#define STG_B  (AT_B + BT_B)         // 32768
#define OFF_B  AT_B
#define NSTG   3
#define GSMEM  (NSTG * STG_B)        // 98304

// ---------------------------------------------------------------------------
// Split-fp16 mma.sync GEMM (NT):
//   C[m,n] = alpha * sum_seg sum_k A_seg[m,k] B[n,k]
// TERMS 3: ah*bh + ah*bl + al*bh  (A = Ah+Ar, B = Bh+Br)
// TERMS 1: ah*bh                  (pure fp16)
// CTA tile 128x128, 8 warps (2m x 4n), warp tile 64x32,
// 3-stage cp.async ring, 2 CTAs/SM.
// Chunks-per-segment is ALWAYS 16 (K1/K2: 512/32, K4: 1024/64).
// EPI 0: fp32 C.  EPI 1: (h, r) fp16 pair.
// ---------------------------------------------------------------------------
template <int EPI, int TERMS>
__global__ __launch_bounds__(256, 2) void gemm_mma(
    const __half* __restrict__ Ahi, const __half* __restrict__ Alo,
    int ldA, size_t aBatch, int aDiv, int aMod, size_t aSeg, int nSeg,
    const __half* __restrict__ Bhi, const __half* __restrict__ Blo,
    int ldB, size_t bBatch, int bDiv, int bMod,
    int K,
    float* __restrict__ Cf,
    __half* __restrict__ Chi, __half* __restrict__ Clo,
    int ldC, size_t cBatch, float alpha)
{
    extern __shared__ char smem[];
    const uint32_t sb = smem_u32(smem);
    const int tid = threadIdx.x;
    const int wid = tid >> 5, lane = tid & 31;
    const int wm = (wid >> 2) * 64;     // 2 m-groups
    const int wn = (wid & 3) * 32;      // 4 n-groups
    const int z = blockIdx.z;
    const int m0 = blockIdx.y * 128;
    const int n0 = blockIdx.x * 128;

    Ahi += (size_t)((z / aDiv) % aMod) * aBatch;
    if (TERMS == 3) Alo += (size_t)((z / aDiv) % aMod) * aBatch;
    Bhi += (size_t)((z / bDiv) % bMod) * bBatch;
    if (TERMS == 3) Blo += (size_t)((z / bDiv) % bMod) * bBatch;

    constexpr int KC  = (TERMS == 3) ? 32 : 64;   // K per chunk
    constexpr int NKS = KC / 16;                  // k16 steps per chunk
    const int total = nSeg * 16;                  // 16 chunks per segment

// seg = ch>>4, k0 = (ch&15)*KC ; base pointers per segment (R12 form)
#define LOAD_CHUNK(ch, stg) do {                                              \
        const int seg_ = (ch) >> 4;                                           \
        const int k0_ = ((ch) & 15) * KC;                                     \
        const uint32_t bb_ = sb + (stg) * STG_B;                              \
        const __half* Ah_ = Ahi + (size_t)seg_ * aSeg;                        \
        if (TERMS == 3) {                                                     \
            const __half* Al_ = Alo + (size_t)seg_ * aSeg;                    \
            _Pragma("unroll")                                                 \
            for (int it = 0; it < 4; it++) {   /* A: 128 rows x 8 pieces */   \
                const int idx = tid + it * 256;                               \
                const int row = idx >> 3;                                     \
                const int p = idx & 7;                                        \
                const __half* src = (p < 4) ? Ah_ : Al_;                      \
                const uint32_t d = row * 128 + SWZC(row, p * 16);             \
                CP16(bb_ + d, (const char*)(src + (size_t)(m0 + row) * ldA    \
                                            + k0_ + (p & 3) * 8));            \
            }                                                                 \
            _Pragma("unroll")                                                 \
            for (int it = 0; it < 4; it++) {  /* B: 128 rows x 8 pieces */    \
                const int idx = tid + it * 256;                               \
                const int row = idx >> 3;                                     \
                const int p = idx & 7;                                        \
                const __half* src = (p < 4) ? Bhi : Blo;                      \
                const uint32_t d = OFF_B + row * 128 + SWZC(row, p * 16);     \
                CP16(bb_ + d, (const char*)(src + (size_t)(n0 + row) * ldB    \
                                            + k0_ + (p & 3) * 8));            \
            }                                                                 \
        } else {            /* hi only, 64 k per row: 128 rows x 8 pieces */  \
            _Pragma("unroll")                                                 \
            for (int it = 0; it < 4; it++) {                                  \
                const int idx = tid + it * 256;                               \
                const int row = idx >> 3;                                     \
                const int p = idx & 7;                                        \
                const uint32_t d = row * 128 + SWZC(row, p * 16);             \
                CP16(bb_ + d, (const char*)(Ah_ + (size_t)(m0 + row) * ldA    \
                                            + k0_ + p * 8));                  \
            }                                                                 \
            _Pragma("unroll")                                                 \
            for (int it = 0; it < 4; it++) {                                  \
                const int idx = tid + it * 256;                               \
                const int row = idx >> 3;                                     \
                const int p = idx & 7;                                        \
                const uint32_t d = OFF_B + row * 128 + SWZC(row, p * 16);     \
                CP16(bb_ + d, (const char*)(Bhi + (size_t)(n0 + row) * ldB    \
                                            + k0_ + p * 8));                  \
            }                                                                 \
        }                                                                     \
    } while (0)

    float acc[4][4][4];
#pragma unroll
    for (int i = 0; i < 4; i++)
#pragma unroll
        for (int j = 0; j < 4; j++)
#pragma unroll
            for (int r = 0; r < 4; r++) acc[i][j][r] = 0.f;

    LOAD_CHUNK(0, 0); CP_COMMIT();
    LOAD_CHUNK(1, 1); CP_COMMIT();

    // per-lane LDSM geometry
    const int aRow = lane & 15;                              // A: 16x16 frags
    const int aCol0 = lane & 16;                             // 0 / 16 bytes
    const int bRow0 = (lane & 7) + ((lane >> 4) & 1) * 8;    // B: 16-row pair
    const int bCol0 = ((lane >> 3) & 1) * 16;

    int stg = 0;                // stage holding chunk `ch`
    for (int ch = 0; ch < total; ch++) {
        CP_WAIT1();
        __syncthreads();

        const uint32_t bb = sb + stg * STG_B;

#pragma unroll
        for (int ks = 0; ks < NKS; ks++) {
            const int colH = ks * 32;
            // --- fragment loads first (B frags + A tile 0) ---
            uint32_t bh[4][2], bl[4][2];
#pragma unroll
            for (int jj = 0; jj < 2; jj++) {
                const int row = wn + jj * 16 + bRow0;
                const uint32_t rb = bb + OFF_B + row * 128;
                LDSM4(&bh[jj * 2][0], rb + SWZC(row, colH + bCol0));
                if (TERMS == 3) LDSM4(&bl[jj * 2][0], rb + SWZC(row, colH + bCol0 + 64));
            }
            uint32_t ahc[4], alc[4], ahn[4], aln[4];
            {
                const int row = wm + aRow;
                const uint32_t ra = bb + row * 128;
                LDSM4(ahc, ra + SWZC(row, colH + aCol0));
                if (TERMS == 3) LDSM4(alc, ra + SWZC(row, colH + aCol0 + 64));
            }
            // --- overlap next chunk's cp.async issue with LDSM latency ---
            if (ks == 0) {
                int nstg = stg + 2; if (nstg >= NSTG) nstg -= NSTG;
                if (ch + 2 < total) { LOAD_CHUNK(ch + 2, nstg); }
                CP_COMMIT();
            }
            // --- MMAs, streaming A tiles one ahead ---
#pragma unroll
            for (int i = 0; i < 4; i++) {
                if (i < 3) {
                    const int row = wm + (i + 1) * 16 + aRow;
                    const uint32_t ra = bb + row * 128;
                    LDSM4(ahn, ra + SWZC(row, colH + aCol0));
                    if (TERMS == 3) LDSM4(aln, ra + SWZC(row, colH + aCol0 + 64));
                }
#pragma unroll
                for (int j = 0; j < 4; j++) MMA(acc[i][j], ahc, bh[j]);
                if (TERMS == 3) {
#pragma unroll
                    for (int j = 0; j < 4; j++) MMA(acc[i][j], ahc, bl[j]);
#pragma unroll
                    for (int j = 0; j < 4; j++) MMA(acc[i][j], alc, bh[j]);
                }
#pragma unroll
                for (int r = 0; r < 4; r++) {
                    ahc[r] = ahn[r];
                    if (TERMS == 3) alc[r] = aln[r];
                }
            }
        }
        stg = stg + 1; if (stg >= NSTG) stg = 0;
    }
#undef LOAD_CHUNK

    // ---- epilogue (vectorized stores) ----
    const int cr = lane >> 2, cc = (lane & 3) * 2;
#pragma unroll
    for (int i = 0; i < 4; i++) {
        const int r0 = m0 + wm + i * 16 + cr;
#pragma unroll
        for (int j = 0; j < 4; j++) {
            const int col = n0 + wn + j * 8 + cc;
            const size_t o0 = (size_t)z * cBatch + (size_t)r0 * ldC + col;
            const size_t o1 = o0 + (size_t)8 * ldC;
            float v0 = acc[i][j][0] * alpha, v1 = acc[i][j][1] * alpha;
            float v2 = acc[i][j][2] * alpha, v3 = acc[i][j][3] * alpha;
            if (EPI == 0) {
                *(float2*)&Cf[o0] = make_float2(v0, v1);
                *(float2*)&Cf[o1] = make_float2(v2, v3);
            } else {
                float h0 = __half2float(__float2half_rn(v0));
                float h1 = __half2float(__float2half_rn(v1));
                float h2 = __half2float(__float2half_rn(v2));
                float h3 = __half2float(__float2half_rn(v3));
                *(__half2*)&Chi[o0] = __floats2half2_rn(v0, v1);
                *(__half2*)&Chi[o1] = __floats2half2_rn(v2, v3);
                *(__half2*)&Clo[o0] = __floats2half2_rn(v0 - h0, v1 - h1);
                *(__half2*)&Clo[o1] = __floats2half2_rn(v2 - h2, v3 - h3);
            }
        }
    }
}

// ---------------------------------------------------------------------------
// Split x -> xs (h/r, [B,N,D]) and xt (h only, [B,D,N])
// ---------------------------------------------------------------------------
__global__ __launch_bounds__(256) void split_x_kernel(const float* __restrict__ x) {
    __shared__ float t[32][33];
    const int b = blockIdx.z;
    const int d0 = blockIdx.x * 32, n0 = blockIdx.y * 32;
    const int tx = threadIdx.x & 31, ty = threadIdx.x >> 5;

    for (int i = ty; i < 32; i += 8)
        t[i][tx] = x[(size_t)b * N_ * D_ + (size_t)(n0 + i) * D_ + d0 + tx];
    __syncthreads();

    for (int i = ty; i < 32; i += 8) {
        float v = t[i][tx];
        __half h = __float2half_rn(v);
        size_t o = (size_t)b * N_ * D_ + (size_t)(n0 + i) * D_ + d0 + tx;
        g_xs_h[o] = h; g_xs_r[o] = __float2half_rn(v - __half2float(h));
    }
    for (int i = ty; i < 32; i += 8) {
        float v = t[tx][i];
        size_t o = (size_t)b * D_ * N_ + (size_t)(d0 + i) * N_ + n0 + tx;
        g_xt_h[o] = __float2half_rn(v);
    }
}

__global__ __launch_bounds__(256) void split_w_kernel(const float* __restrict__ W) {
    __shared__ float t[32][33];
    const int h = blockIdx.z;
    const int e0 = blockIdx.x * 32, d0 = blockIdx.y * 32;
    const int tx = threadIdx.x & 31, ty = threadIdx.x >> 5;

    for (int i = ty; i < 32; i += 8)
        t[i][tx] = W[(size_t)h * D_ * D_ + (size_t)(d0 + i) * D_ + e0 + tx];
    __syncthreads();

    for (int i = ty; i < 32; i += 8) {
        float v = t[tx][i];   // W[d0+tx][e0+i]
        __half hh = __float2half_rn(v);
        size_t o = (size_t)h * D_ * D_ + (size_t)(e0 + i) * D_ + d0 + tx;
        g_Wt_h[o] = hh; g_Wt_r[o] = __float2half_rn(v - __half2float(hh));
    }
}

// ---------------------------------------------------------------------------
// Softmax over rows of g_S; writes fp16 P (hi only)
// ---------------------------------------------------------------------------
__global__ __launch_bounds__(256) void softmax_split_kernel() {
    const size_t row = blockIdx.x;
    const float* p = g_S + row * N_;
    const int tid = threadIdx.x;
    __shared__ float red[8];

    float4 v = *(const float4*)&p[tid * 4];
    float m = fmaxf(fmaxf(v.x, v.y), fmaxf(v.z, v.w));
#pragma unroll
    for (int o = 16; o; o >>= 1) m = fmaxf(m, __shfl_xor_sync(0xFFFFFFFFu, m, o));
    if ((tid & 31) == 0) red[tid >> 5] = m;
    __syncthreads();
    float bm = red[0];
#pragma unroll
    for (int i = 1; i < 8; i++) bm = fmaxf(bm, red[i]);
    __syncthreads();

    v.x = __expf(v.x - bm); v.y = __expf(v.y - bm);
    v.z = __expf(v.z - bm); v.w = __expf(v.w - bm);
    float s = v.x + v.y + v.z + v.w;
#pragma unroll
    for (int o = 16; o; o >>= 1) s += __shfl_xor_sync(0xFFFFFFFFu, s, o);
    if ((tid & 31) == 0) red[tid >> 5] = s;
    __syncthreads();
    float bs = 0.f;
#pragma unroll
    for (int i = 0; i < 8; i++) bs += red[i];
    float inv = 1.0f / bs;

    __half2* dst = (__half2*)&g_P_h[row * N_ + tid * 4];
    dst[0] = __floats2half2_rn(v.x * inv, v.y * inv);
    dst[1] = __floats2half2_rn(v.z * inv, v.w * inv);
}

// ---------------------------------------------------------------------------
extern "C" void kernel_launch(void* const* d_in, const int* in_sizes, int n_in,
                              void* d_out, int out_size) {
    const float* x = (const float*)d_in[0];   // [8,1024,512]
    const float* W = (const float*)d_in[1];   // [4,512,512]
    float* out = (float*)d_out;               // [8,1024,512]

    cudaFuncSetAttribute(gemm_mma<0, 3>, cudaFuncAttributeMaxDynamicSharedMemorySize, GSMEM);
    cudaFuncSetAttribute(gemm_mma<1, 3>, cudaFuncAttributeMaxDynamicSharedMemorySize, GSMEM);
    cudaFuncSetAttribute(gemm_mma<0, 1>, cudaFuncAttributeMaxDynamicSharedMemorySize, GSMEM);

    __half *xs_h, *xs_r, *xt_h, *Wt_h, *Wt_r, *Y_h, *Y_r, *P_h;
    float* Sf;
    cudaGetSymbolAddress((void**)&xs_h, g_xs_h);
    cudaGetSymbolAddress((void**)&xs_r, g_xs_r);
    cudaGetSymbolAddress((void**)&xt_h, g_xt_h);
    cudaGetSymbolAddress((void**)&Wt_h, g_Wt_h);
    cudaGetSymbolAddress((void**)&Wt_r, g_Wt_r);
    cudaGetSymbolAddress((void**)&Y_h, g_Y_h);
    cudaGetSymbolAddress((void**)&Y_r, g_Y_r);
    cudaGetSymbolAddress((void**)&P_h, g_P_h);
    cudaGetSymbolAddress((void**)&Sf, g_S);

    const float SCALE = 0.04419417382415922f;   // 512^-0.5

    split_x_kernel<<<dim3(D_ / 32, N_ / 32, B_), 256>>>(x);
    split_w_kernel<<<dim3(D_ / 32, D_ / 32, H_), 256>>>(W);

    // K1: Y[b,h] = xs[b] @ Wt[h]^T  (3-term) -> fp16 h/r Y
    gemm_mma<1, 3><<<dim3(D_ / 128, N_ / 128, B_ * H_), 256, GSMEM>>>(
        xs_h, xs_r, D_, (size_t)N_ * D_, 4, 8, 0, 1,
        Wt_h, Wt_r, D_, (size_t)D_ * D_, 1, 4,
        D_,
        nullptr, Y_h, Y_r, D_, (size_t)N_ * D_, 1.0f);

    // K2: S[b,h] = scale * Y[b,h] @ xs[b]^T  (3-term) -> fp32
    gemm_mma<0, 3><<<dim3(N_ / 128, N_ / 128, B_ * H_), 256, GSMEM>>>(
        Y_h, Y_r, D_, (size_t)N_ * D_, 1, 32, 0, 1,
        xs_h, xs_r, D_, (size_t)N_ * D_, 4, 8,
        D_,
        Sf, nullptr, nullptr, N_, (size_t)N_ * N_, SCALE);

    softmax_split_kernel<<<B_ * H_ * N_, 256>>>();

    // K4: out[b] = 0.25 * sum_h P_h[b,h] @ xt_h[b]^T  (1-term fp16,
    //     4 head-segments accumulated in registers, direct out write)
    gemm_mma<0, 1><<<dim3(D_ / 128, N_ / 128, B_), 256, GSMEM>>>(
        P_h, nullptr, N_, (size_t)H_ * N_ * N_, 1, 8, (size_t)N_ * N_, H_,
        xt_h, nullptr, N_, (size_t)D_ * N_, 1, 8,
        N_,
        out, nullptr, nullptr, D_, (size_t)N_ * D_, 0.25f);
}

// round 15
// speedup vs baseline: 1.5903x; 1.0354x over previous
#include <cuda_runtime.h>
#include <cuda_fp16.h>
#include <cstdint>
#include <math.h>

#define B_ 8
#define N_ 1024
#define D_ 512
#define H_ 4

// ---------------------------------------------------------------------------
// Scratch (device globals; no allocation allowed)
// ---------------------------------------------------------------------------
__device__ __align__(16) __half g_xs_h[(size_t)B_ * N_ * D_];
__device__ __align__(16) __half g_xs_r[(size_t)B_ * N_ * D_];
__device__ __align__(16) __half g_xt_h[(size_t)B_ * D_ * N_];
__device__ __align__(16) __half g_Wt_h[(size_t)H_ * D_ * D_];
__device__ __align__(16) __half g_Wt_r[(size_t)H_ * D_ * D_];
__device__ __align__(16) __half g_Y_h[(size_t)B_ * H_ * N_ * D_];
__device__ __align__(16) __half g_Y_r[(size_t)B_ * H_ * N_ * D_];
__device__ __align__(16) float  g_S  [(size_t)B_ * H_ * N_ * N_];
__device__ __align__(16) __half g_P_h[(size_t)B_ * H_ * N_ * N_];

// ---------------------------------------------------------------------------
// helpers (portable sm_80+ PTX)
// ---------------------------------------------------------------------------
__device__ __forceinline__ uint32_t smem_u32(const void* p) {
    uint32_t a;
    asm("{ .reg .u64 t; cvta.to.shared.u64 t, %1; cvt.u32.u64 %0, t; }"
        : "=r"(a) : "l"(p));
    return a;
}

#define CP16(dst, src) \
    asm volatile("cp.async.cg.shared.global [%0], [%1], 16;" \
                 :: "r"(dst), "l"(src))
#define CP_COMMIT() asm volatile("cp.async.commit_group;" ::: "memory")
#define CP_WAIT1()  asm volatile("cp.async.wait_group 1;"  ::: "memory")

#define LDSM4(r, a)                                                           \
    asm volatile("ldmatrix.sync.aligned.m8n8.x4.shared.b16 {%0,%1,%2,%3}, [%4];" \
                 : "=r"((r)[0]), "=r"((r)[1]), "=r"((r)[2]), "=r"((r)[3])     \
                 : "r"(a))

#define MMA(c, a, b)                                                          \
    asm volatile("mma.sync.aligned.m16n8k16.row.col.f32.f16.f16.f32 "         \
                 "{%0,%1,%2,%3},{%4,%5,%6,%7},{%8,%9},{%0,%1,%2,%3};"         \
                 : "+f"((c)[0]), "+f"((c)[1]), "+f"((c)[2]), "+f"((c)[3])     \
                 : "r"((a)[0]), "r"((a)[1]), "r"((a)[2]), "r"((a)[3]),        \
                   "r"((b)[0]), "r"((b)[1]))

// swizzle within a 128B row
#define SWZC(row, colB) ((uint32_t)(colB) ^ (((uint32_t)(row) & 7u) << 4))

// smem stages: 32KB each, 3 stages.
// TERMS=3: K-chunk 32, row = [hi k0..31 | lo k0..31] (128B)
// TERMS=1: K-chunk 64, row = [hi k0..63] (128B)
#define AT_B   (128 * 128)           // 16384
#define BT_B   (128 * 128)           // 16384
#define STG_B  (AT_B + BT_B)         // 32768
#define OFF_B  AT_B
#define NSTG   3
#define GSMEM  (NSTG * STG_B)        // 98304

// ---------------------------------------------------------------------------
// Split-fp16 mma.sync GEMM (NT):
//   C[m,n] = alpha * sum_seg sum_k A_seg[m,k] B[n,k]
// TERMS 3: ah*bh + ah*bl + al*bh  (A = Ah+Ar, B = Bh+Br)
// TERMS 1: ah*bh                  (pure fp16)
// NSEG is compile-time; NSEG==1 removes all segment arithmetic.
// CTA tile 128x128, 8 warps (2m x 4n), warp tile 64x32,
// 3-stage cp.async ring, 2 CTAs/SM.  16 chunks per segment always.
// EPI 0: fp32 C.  EPI 1: (h, r) fp16 pair.
// ---------------------------------------------------------------------------
template <int EPI, int TERMS, int NSEG>
__global__ __launch_bounds__(256, 2) void gemm_mma(
    const __half* __restrict__ Ahi, const __half* __restrict__ Alo,
    int ldA, size_t aBatch, int aDiv, int aMod, size_t aSeg,
    const __half* __restrict__ Bhi, const __half* __restrict__ Blo,
    int ldB, size_t bBatch, int bDiv, int bMod,
    float* __restrict__ Cf,
    __half* __restrict__ Chi, __half* __restrict__ Clo,
    int ldC, size_t cBatch, float alpha)
{
    extern __shared__ char smem[];
    const uint32_t sb = smem_u32(smem);
    const int tid = threadIdx.x;
    const int wid = tid >> 5, lane = tid & 31;
    const int wm = (wid >> 2) * 64;     // 2 m-groups
    const int wn = (wid & 3) * 32;      // 4 n-groups
    const int z = blockIdx.z;
    const int m0 = blockIdx.y * 128;
    const int n0 = blockIdx.x * 128;

    Ahi += (size_t)((z / aDiv) % aMod) * aBatch;
    if (TERMS == 3) Alo += (size_t)((z / aDiv) % aMod) * aBatch;
    Bhi += (size_t)((z / bDiv) % bMod) * bBatch;
    if (TERMS == 3) Blo += (size_t)((z / bDiv) % bMod) * bBatch;

    constexpr int KC    = (TERMS == 3) ? 32 : 64;   // K per chunk
    constexpr int NKS   = KC / 16;                  // k16 steps per chunk
    constexpr int TOTAL = NSEG * 16;                // 16 chunks per segment

// NSEG==1: no segment offset at all. Else seg = ch>>4 (shift only).
#define LOAD_CHUNK(ch, stg) do {                                              \
        const int k0_ = ((ch) & 15) * KC;                                     \
        const uint32_t bb_ = sb + (stg) * STG_B;                              \
        const __half* Ah_ = (NSEG == 1) ? Ahi                                 \
                           : Ahi + (size_t)((ch) >> 4) * aSeg;                \
        if (TERMS == 3) {                                                     \
            const __half* Al_ = (NSEG == 1) ? Alo                             \
                               : Alo + (size_t)((ch) >> 4) * aSeg;            \
            _Pragma("unroll")                                                 \
            for (int it = 0; it < 4; it++) {   /* A: 128 rows x 8 pieces */   \
                const int idx = tid + it * 256;                               \
                const int row = idx >> 3;                                     \
                const int p = idx & 7;                                        \
                const __half* src = (p < 4) ? Ah_ : Al_;                      \
                const uint32_t d = row * 128 + SWZC(row, p * 16);             \
                CP16(bb_ + d, (const char*)(src + (size_t)(m0 + row) * ldA    \
                                            + k0_ + (p & 3) * 8));            \
            }                                                                 \
            _Pragma("unroll")                                                 \
            for (int it = 0; it < 4; it++) {  /* B: 128 rows x 8 pieces */    \
                const int idx = tid + it * 256;                               \
                const int row = idx >> 3;                                     \
                const int p = idx & 7;                                        \
                const __half* src = (p < 4) ? Bhi : Blo;                      \
                const uint32_t d = OFF_B + row * 128 + SWZC(row, p * 16);     \
                CP16(bb_ + d, (const char*)(src + (size_t)(n0 + row) * ldB    \
                                            + k0_ + (p & 3) * 8));            \
            }                                                                 \
        } else {            /* hi only, 64 k per row: 128 rows x 8 pieces */  \
            _Pragma("unroll")                                                 \
            for (int it = 0; it < 4; it++) {                                  \
                const int idx = tid + it * 256;                               \
                const int row = idx >> 3;                                     \
                const int p = idx & 7;                                        \
                const uint32_t d = row * 128 + SWZC(row, p * 16);             \
                CP16(bb_ + d, (const char*)(Ah_ + (size_t)(m0 + row) * ldA    \
                                            + k0_ + p * 8));                  \
            }                                                                 \
            _Pragma("unroll")                                                 \
            for (int it = 0; it < 4; it++) {                                  \
                const int idx = tid + it * 256;                               \
                const int row = idx >> 3;                                     \
                const int p = idx & 7;                                        \
                const uint32_t d = OFF_B + row * 128 + SWZC(row, p * 16);     \
                CP16(bb_ + d, (const char*)(Bhi + (size_t)(n0 + row) * ldB    \
                                            + k0_ + p * 8));                  \
            }                                                                 \
        }                                                                     \
    } while (0)

    float acc[4][4][4];
#pragma unroll
    for (int i = 0; i < 4; i++)
#pragma unroll
        for (int j = 0; j < 4; j++)
#pragma unroll
            for (int r = 0; r < 4; r++) acc[i][j][r] = 0.f;

    LOAD_CHUNK(0, 0); CP_COMMIT();
    LOAD_CHUNK(1, 1); CP_COMMIT();

    // per-lane LDSM geometry
    const int aRow = lane & 15;                              // A: 16x16 frags
    const int aCol0 = lane & 16;                             // 0 / 16 bytes
    const int bRow0 = (lane & 7) + ((lane >> 4) & 1) * 8;    // B: 16-row pair
    const int bCol0 = ((lane >> 3) & 1) * 16;

    int stg = 0;                // stage holding chunk `ch`
    for (int ch = 0; ch < TOTAL; ch++) {
        CP_WAIT1();
        __syncthreads();

        const uint32_t bb = sb + stg * STG_B;

#pragma unroll
        for (int ks = 0; ks < NKS; ks++) {
            const int colH = ks * 32;
            // --- fragment loads first (B frags + A tile 0) ---
            uint32_t bh[4][2], bl[4][2];
#pragma unroll
            for (int jj = 0; jj < 2; jj++) {
                const int row = wn + jj * 16 + bRow0;
                const uint32_t rb = bb + OFF_B + row * 128;
                LDSM4(&bh[jj * 2][0], rb + SWZC(row, colH + bCol0));
                if (TERMS == 3) LDSM4(&bl[jj * 2][0], rb + SWZC(row, colH + bCol0 + 64));
            }
            uint32_t ahc[4], alc[4], ahn[4], aln[4];
            {
                const int row = wm + aRow;
                const uint32_t ra = bb + row * 128;
                LDSM4(ahc, ra + SWZC(row, colH + aCol0));
                if (TERMS == 3) LDSM4(alc, ra + SWZC(row, colH + aCol0 + 64));
            }
            // --- overlap next chunk's cp.async issue with LDSM latency ---
            if (ks == 0) {
                int nstg = stg + 2; if (nstg >= NSTG) nstg -= NSTG;
                if (ch + 2 < TOTAL) { LOAD_CHUNK(ch + 2, nstg); }
                CP_COMMIT();
            }
            // --- MMAs, streaming A tiles one ahead ---
#pragma unroll
            for (int i = 0; i < 4; i++) {
                if (i < 3) {
                    const int row = wm + (i + 1) * 16 + aRow;
                    const uint32_t ra = bb + row * 128;
                    LDSM4(ahn, ra + SWZC(row, colH + aCol0));
                    if (TERMS == 3) LDSM4(aln, ra + SWZC(row, colH + aCol0 + 64));
                }
#pragma unroll
                for (int j = 0; j < 4; j++) MMA(acc[i][j], ahc, bh[j]);
                if (TERMS == 3) {
#pragma unroll
                    for (int j = 0; j < 4; j++) MMA(acc[i][j], ahc, bl[j]);
#pragma unroll
                    for (int j = 0; j < 4; j++) MMA(acc[i][j], alc, bh[j]);
                }
#pragma unroll
                for (int r = 0; r < 4; r++) {
                    ahc[r] = ahn[r];
                    if (TERMS == 3) alc[r] = aln[r];
                }
            }
        }
        stg = stg + 1; if (stg >= NSTG) stg = 0;
    }
#undef LOAD_CHUNK

    // ---- epilogue (vectorized stores) ----
    const int cr = lane >> 2, cc = (lane & 3) * 2;
#pragma unroll
    for (int i = 0; i < 4; i++) {
        const int r0 = m0 + wm + i * 16 + cr;
#pragma unroll
        for (int j = 0; j < 4; j++) {
            const int col = n0 + wn + j * 8 + cc;
            const size_t o0 = (size_t)z * cBatch + (size_t)r0 * ldC + col;
            const size_t o1 = o0 + (size_t)8 * ldC;
            float v0 = acc[i][j][0] * alpha, v1 = acc[i][j][1] * alpha;
            float v2 = acc[i][j][2] * alpha, v3 = acc[i][j][3] * alpha;
            if (EPI == 0) {
                *(float2*)&Cf[o0] = make_float2(v0, v1);
                *(float2*)&Cf[o1] = make_float2(v2, v3);
            } else {
                float h0 = __half2float(__float2half_rn(v0));
                float h1 = __half2float(__float2half_rn(v1));
                float h2 = __half2float(__float2half_rn(v2));
                float h3 = __half2float(__float2half_rn(v3));
                *(__half2*)&Chi[o0] = __floats2half2_rn(v0, v1);
                *(__half2*)&Chi[o1] = __floats2half2_rn(v2, v3);
                *(__half2*)&Clo[o0] = __floats2half2_rn(v0 - h0, v1 - h1);
                *(__half2*)&Clo[o1] = __floats2half2_rn(v2 - h2, v3 - h3);
            }
        }
    }
}

// ---------------------------------------------------------------------------
// Split x -> xs (h/r, [B,N,D]) and xt (h only, [B,D,N])
// ---------------------------------------------------------------------------
__global__ __launch_bounds__(256) void split_x_kernel(const float* __restrict__ x) {
    __shared__ float t[32][33];
    const int b = blockIdx.z;
    const int d0 = blockIdx.x * 32, n0 = blockIdx.y * 32;
    const int tx = threadIdx.x & 31, ty = threadIdx.x >> 5;

    for (int i = ty; i < 32; i += 8)
        t[i][tx] = x[(size_t)b * N_ * D_ + (size_t)(n0 + i) * D_ + d0 + tx];
    __syncthreads();

    for (int i = ty; i < 32; i += 8) {
        float v = t[i][tx];
        __half h = __float2half_rn(v);
        size_t o = (size_t)b * N_ * D_ + (size_t)(n0 + i) * D_ + d0 + tx;
        g_xs_h[o] = h; g_xs_r[o] = __float2half_rn(v - __half2float(h));
    }
    for (int i = ty; i < 32; i += 8) {
        float v = t[tx][i];
        size_t o = (size_t)b * D_ * N_ + (size_t)(d0 + i) * N_ + n0 + tx;
        g_xt_h[o] = __float2half_rn(v);
    }
}

__global__ __launch_bounds__(256) void split_w_kernel(const float* __restrict__ W) {
    __shared__ float t[32][33];
    const int h = blockIdx.z;
    const int e0 = blockIdx.x * 32, d0 = blockIdx.y * 32;
    const int tx = threadIdx.x & 31, ty = threadIdx.x >> 5;

    for (int i = ty; i < 32; i += 8)
        t[i][tx] = W[(size_t)h * D_ * D_ + (size_t)(d0 + i) * D_ + e0 + tx];
    __syncthreads();

    for (int i = ty; i < 32; i += 8) {
        float v = t[tx][i];   // W[d0+tx][e0+i]
        __half hh = __float2half_rn(v);
        size_t o = (size_t)h * D_ * D_ + (size_t)(e0 + i) * D_ + d0 + tx;
        g_Wt_h[o] = hh; g_Wt_r[o] = __float2half_rn(v - __half2float(hh));
    }
}

// ---------------------------------------------------------------------------
// Softmax: one row per WARP (no smem, no __syncthreads).
// Block = 8 warps = 8 rows; each lane holds 32 elems (8 float4s).
// ---------------------------------------------------------------------------
__global__ __launch_bounds__(256) void softmax_warp_kernel() {
    const int wid = threadIdx.x >> 5, lane = threadIdx.x & 31;
    const size_t row = (size_t)blockIdx.x * 8 + wid;
    const float* p = g_S + row * N_;

    float4 v[8];
    float m = -1e30f;
#pragma unroll
    for (int i = 0; i < 8; i++) {
        v[i] = *(const float4*)&p[(i * 32 + lane) * 4];
        m = fmaxf(m, fmaxf(fmaxf(v[i].x, v[i].y), fmaxf(v[i].z, v[i].w)));
    }
#pragma unroll
    for (int o = 16; o; o >>= 1) m = fmaxf(m, __shfl_xor_sync(0xFFFFFFFFu, m, o));

    float s = 0.f;
#pragma unroll
    for (int i = 0; i < 8; i++) {
        v[i].x = __expf(v[i].x - m); v[i].y = __expf(v[i].y - m);
        v[i].z = __expf(v[i].z - m); v[i].w = __expf(v[i].w - m);
        s += (v[i].x + v[i].y) + (v[i].z + v[i].w);
    }
#pragma unroll
    for (int o = 16; o; o >>= 1) s += __shfl_xor_sync(0xFFFFFFFFu, s, o);
    const float inv = 1.0f / s;

    __half2* dst = (__half2*)&g_P_h[row * N_];
#pragma unroll
    for (int i = 0; i < 8; i++) {
        const int e = (i * 32 + lane) * 2;   // half2 index
        dst[e]     = __floats2half2_rn(v[i].x * inv, v[i].y * inv);
        dst[e + 1] = __floats2half2_rn(v[i].z * inv, v[i].w * inv);
    }
}

// ---------------------------------------------------------------------------
extern "C" void kernel_launch(void* const* d_in, const int* in_sizes, int n_in,
                              void* d_out, int out_size) {
    const float* x = (const float*)d_in[0];   // [8,1024,512]
    const float* W = (const float*)d_in[1];   // [4,512,512]
    float* out = (float*)d_out;               // [8,1024,512]

    cudaFuncSetAttribute(gemm_mma<0, 3, 1>, cudaFuncAttributeMaxDynamicSharedMemorySize, GSMEM);
    cudaFuncSetAttribute(gemm_mma<1, 3, 1>, cudaFuncAttributeMaxDynamicSharedMemorySize, GSMEM);
    cudaFuncSetAttribute(gemm_mma<0, 1, 4>, cudaFuncAttributeMaxDynamicSharedMemorySize, GSMEM);

    __half *xs_h, *xs_r, *xt_h, *Wt_h, *Wt_r, *Y_h, *Y_r, *P_h;
    float* Sf;
    cudaGetSymbolAddress((void**)&xs_h, g_xs_h);
    cudaGetSymbolAddress((void**)&xs_r, g_xs_r);
    cudaGetSymbolAddress((void**)&xt_h, g_xt_h);
    cudaGetSymbolAddress((void**)&Wt_h, g_Wt_h);
    cudaGetSymbolAddress((void**)&Wt_r, g_Wt_r);
    cudaGetSymbolAddress((void**)&Y_h, g_Y_h);
    cudaGetSymbolAddress((void**)&Y_r, g_Y_r);
    cudaGetSymbolAddress((void**)&P_h, g_P_h);
    cudaGetSymbolAddress((void**)&Sf, g_S);

    const float SCALE = 0.04419417382415922f;   // 512^-0.5

    split_x_kernel<<<dim3(D_ / 32, N_ / 32, B_), 256>>>(x);
    split_w_kernel<<<dim3(D_ / 32, D_ / 32, H_), 256>>>(W);

    // K1: Y[b,h] = xs[b] @ Wt[h]^T  (3-term, NSEG=1) -> fp16 h/r Y
    gemm_mma<1, 3, 1><<<dim3(D_ / 128, N_ / 128, B_ * H_), 256, GSMEM>>>(
        xs_h, xs_r, D_, (size_t)N_ * D_, 4, 8, 0,
        Wt_h, Wt_r, D_, (size_t)D_ * D_, 1, 4,
        nullptr, Y_h, Y_r, D_, (size_t)N_ * D_, 1.0f);

    // K2: S[b,h] = scale * Y[b,h] @ xs[b]^T  (3-term, NSEG=1) -> fp32
    gemm_mma<0, 3, 1><<<dim3(N_ / 128, N_ / 128, B_ * H_), 256, GSMEM>>>(
        Y_h, Y_r, D_, (size_t)N_ * D_, 1, 32, 0,
        xs_h, xs_r, D_, (size_t)N_ * D_, 4, 8,
        Sf, nullptr, nullptr, N_, (size_t)N_ * N_, SCALE);

    softmax_warp_kernel<<<(B_ * H_ * N_) / 8, 256>>>();

    // K4: out[b] = 0.25 * sum_h P_h[b,h] @ xt_h[b]^T  (1-term fp16, NSEG=4)
    gemm_mma<0, 1, 4><<<dim3(D_ / 128, N_ / 128, B_), 256, GSMEM>>>(
        P_h, nullptr, N_, (size_t)H_ * N_ * N_, 1, 8, (size_t)N_ * N_,
        xt_h, nullptr, N_, (size_t)D_ * N_, 1, 8,
        out, nullptr, nullptr, D_, (size_t)N_ * D_, 0.25f);
}

// round 17
// speedup vs baseline: 1.5968x; 1.0041x over previous
#include <cuda_runtime.h>
#include <cuda_fp16.h>
#include <cstdint>
#include <math.h>

#define B_ 8
#define N_ 1024
#define D_ 512
#define H_ 4

// ---------------------------------------------------------------------------
// Scratch (device globals; no allocation allowed)
// ---------------------------------------------------------------------------
__device__ __align__(16) __half g_xs_h[(size_t)B_ * N_ * D_];
__device__ __align__(16) __half g_xs_r[(size_t)B_ * N_ * D_];
__device__ __align__(16) __half g_xt_h[(size_t)B_ * D_ * N_];
__device__ __align__(16) __half g_Wt_h[(size_t)H_ * D_ * D_];
__device__ __align__(16) __half g_Wt_r[(size_t)H_ * D_ * D_];
__device__ __align__(16) __half g_Y_h[(size_t)B_ * H_ * N_ * D_];
__device__ __align__(16) __half g_Y_r[(size_t)B_ * H_ * N_ * D_];
__device__ __align__(16) float  g_S  [(size_t)B_ * H_ * N_ * N_];
__device__ __align__(16) __half g_P_h[(size_t)B_ * H_ * N_ * N_];

// ---------------------------------------------------------------------------
// helpers (portable sm_80+ PTX)
// ---------------------------------------------------------------------------
__device__ __forceinline__ uint32_t smem_u32(const void* p) {
    uint32_t a;
    asm("{ .reg .u64 t; cvta.to.shared.u64 t, %1; cvt.u32.u64 %0, t; }"
        : "=r"(a) : "l"(p));
    return a;
}

#define CP16(dst, src) \
    asm volatile("cp.async.cg.shared.global [%0], [%1], 16;" \
                 :: "r"(dst), "l"(src))
#define CP_COMMIT() asm volatile("cp.async.commit_group;" ::: "memory")
#define CP_WAIT1()  asm volatile("cp.async.wait_group 1;"  ::: "memory")

#define LDSM4(r, a)                                                           \
    asm volatile("ldmatrix.sync.aligned.m8n8.x4.shared.b16 {%0,%1,%2,%3}, [%4];" \
                 : "=r"((r)[0]), "=r"((r)[1]), "=r"((r)[2]), "=r"((r)[3])     \
                 : "r"(a))

#define MMA(c, a, b)                                                          \
    asm volatile("mma.sync.aligned.m16n8k16.row.col.f32.f16.f16.f32 "         \
                 "{%0,%1,%2,%3},{%4,%5,%6,%7},{%8,%9},{%0,%1,%2,%3};"         \
                 : "+f"((c)[0]), "+f"((c)[1]), "+f"((c)[2]), "+f"((c)[3])     \
                 : "r"((a)[0]), "r"((a)[1]), "r"((a)[2]), "r"((a)[3]),        \
                   "r"((b)[0]), "r"((b)[1]))

// swizzle within a 128B row
#define SWZC(row, colB) ((uint32_t)(colB) ^ (((uint32_t)(row) & 7u) << 4))

// smem stages: 32KB each, 3 stages.
// TERMS=3: K-chunk 32, row = [hi k0..31 | lo k0..31] (128B)
// TERMS=1: K-chunk 64, row = [hi k0..63] (128B)
#define AT_B   (128 * 128)           // 16384
#define BT_B   (128 * 128)           // 16384
#define STG_B  (AT_B + BT_B)         // 32768
#define OFF_B  AT_B
#define NSTG   3
#define GSMEM  (NSTG * STG_B)        // 98304

// ---------------------------------------------------------------------------
// Split-fp16 mma.sync GEMM (NT):
//   C[m,n] = alpha * sum_seg sum_k A_seg[m,k] B[n,k]
// TERMS 3: ah*bh + ah*bl + al*bh  (A = Ah+Ar, B = Bh+Br)
// TERMS 1: ah*bh                  (pure fp16)
// NSEG is compile-time; NSEG==1 removes all segment arithmetic.
// CTA tile 128x128, 8 warps (2m x 4n), warp tile 64x32,
// 3-stage cp.async ring, 2 CTAs/SM.  16 chunks per segment always.
// EPI 0: fp32 C.  EPI 1: (h, r) fp16 pair.
// ---------------------------------------------------------------------------
template <int EPI, int TERMS, int NSEG>
__global__ __launch_bounds__(256, 2) void gemm_mma(
    const __half* __restrict__ Ahi, const __half* __restrict__ Alo,
    int ldA, size_t aBatch, int aDiv, int aMod, size_t aSeg,
    const __half* __restrict__ Bhi, const __half* __restrict__ Blo,
    int ldB, size_t bBatch, int bDiv, int bMod,
    float* __restrict__ Cf,
    __half* __restrict__ Chi, __half* __restrict__ Clo,
    int ldC, size_t cBatch, float alpha)
{
    extern __shared__ char smem[];
    const uint32_t sb = smem_u32(smem);
    const int tid = threadIdx.x;
    const int wid = tid >> 5, lane = tid & 31;
    const int wm = (wid >> 2) * 64;     // 2 m-groups
    const int wn = (wid & 3) * 32;      // 4 n-groups
    const int z = blockIdx.z;
    const int m0 = blockIdx.y * 128;
    const int n0 = blockIdx.x * 128;

    Ahi += (size_t)((z / aDiv) % aMod) * aBatch;
    if (TERMS == 3) Alo += (size_t)((z / aDiv) % aMod) * aBatch;
    Bhi += (size_t)((z / bDiv) % bMod) * bBatch;
    if (TERMS == 3) Blo += (size_t)((z / bDiv) % bMod) * bBatch;

    constexpr int KC    = (TERMS == 3) ? 32 : 64;   // K per chunk
    constexpr int NKS   = KC / 16;                  // k16 steps per chunk
    constexpr int TOTAL = NSEG * 16;                // 16 chunks per segment

// NSEG==1: no segment offset at all. Else seg = ch>>4 (shift only).
#define LOAD_CHUNK(ch, stg) do {                                              \
        const int k0_ = ((ch) & 15) * KC;                                     \
        const uint32_t bb_ = sb + (stg) * STG_B;                              \
        const __half* Ah_ = (NSEG == 1) ? Ahi                                 \
                           : Ahi + (size_t)((ch) >> 4) * aSeg;                \
        if (TERMS == 3) {                                                     \
            const __half* Al_ = (NSEG == 1) ? Alo                             \
                               : Alo + (size_t)((ch) >> 4) * aSeg;            \
            _Pragma("unroll")                                                 \
            for (int it = 0; it < 4; it++) {   /* A: 128 rows x 8 pieces */   \
                const int idx = tid + it * 256;                               \
                const int row = idx >> 3;                                     \
                const int p = idx & 7;                                        \
                const __half* src = (p < 4) ? Ah_ : Al_;                      \
                const uint32_t d = row * 128 + SWZC(row, p * 16);             \
                CP16(bb_ + d, (const char*)(src + (size_t)(m0 + row) * ldA    \
                                            + k0_ + (p & 3) * 8));            \
            }                                                                 \
            _Pragma("unroll")                                                 \
            for (int it = 0; it < 4; it++) {  /* B: 128 rows x 8 pieces */    \
                const int idx = tid + it * 256;                               \
                const int row = idx >> 3;                                     \
                const int p = idx & 7;                                        \
                const __half* src = (p < 4) ? Bhi : Blo;                      \
                const uint32_t d = OFF_B + row * 128 + SWZC(row, p * 16);     \
                CP16(bb_ + d, (const char*)(src + (size_t)(n0 + row) * ldB    \
                                            + k0_ + (p & 3) * 8));            \
            }                                                                 \
        } else {            /* hi only, 64 k per row: 128 rows x 8 pieces */  \
            _Pragma("unroll")                                                 \
            for (int it = 0; it < 4; it++) {                                  \
                const int idx = tid + it * 256;                               \
                const int row = idx >> 3;                                     \
                const int p = idx & 7;                                        \
                const uint32_t d = row * 128 + SWZC(row, p * 16);             \
                CP16(bb_ + d, (const char*)(Ah_ + (size_t)(m0 + row) * ldA    \
                                            + k0_ + p * 8));                  \
            }                                                                 \
            _Pragma("unroll")                                                 \
            for (int it = 0; it < 4; it++) {                                  \
                const int idx = tid + it * 256;                               \
                const int row = idx >> 3;                                     \
                const int p = idx & 7;                                        \
                const uint32_t d = OFF_B + row * 128 + SWZC(row, p * 16);     \
                CP16(bb_ + d, (const char*)(Bhi + (size_t)(n0 + row) * ldB    \
                                            + k0_ + p * 8));                  \
            }                                                                 \
        }                                                                     \
    } while (0)

    float acc[4][4][4];
#pragma unroll
    for (int i = 0; i < 4; i++)
#pragma unroll
        for (int j = 0; j < 4; j++)
#pragma unroll
            for (int r = 0; r < 4; r++) acc[i][j][r] = 0.f;

    LOAD_CHUNK(0, 0); CP_COMMIT();
    LOAD_CHUNK(1, 1); CP_COMMIT();

    // per-lane LDSM geometry
    const int aRow = lane & 15;                              // A: 16x16 frags
    const int aCol0 = lane & 16;                             // 0 / 16 bytes
    const int bRow0 = (lane & 7) + ((lane >> 4) & 1) * 8;    // B: 16-row pair
    const int bCol0 = ((lane >> 3) & 1) * 16;

    int stg = 0;                // stage holding chunk `ch`
    for (int ch = 0; ch < TOTAL; ch++) {
        CP_WAIT1();
        __syncthreads();

        const uint32_t bb = sb + stg * STG_B;

#pragma unroll
        for (int ks = 0; ks < NKS; ks++) {
            const int colH = ks * 32;
            // --- fragment loads first (B frags + A tile 0) ---
            uint32_t bh[4][2], bl[4][2];
#pragma unroll
            for (int jj = 0; jj < 2; jj++) {
                const int row = wn + jj * 16 + bRow0;
                const uint32_t rb = bb + OFF_B + row * 128;
                LDSM4(&bh[jj * 2][0], rb + SWZC(row, colH + bCol0));
                if (TERMS == 3) LDSM4(&bl[jj * 2][0], rb + SWZC(row, colH + bCol0 + 64));
            }
            uint32_t ahc[4], alc[4], ahn[4], aln[4];
            {
                const int row = wm + aRow;
                const uint32_t ra = bb + row * 128;
                LDSM4(ahc, ra + SWZC(row, colH + aCol0));
                if (TERMS == 3) LDSM4(alc, ra + SWZC(row, colH + aCol0 + 64));
            }
            // --- overlap next chunk's cp.async issue with LDSM latency ---
            if (ks == 0) {
                int nstg = stg + 2; if (nstg >= NSTG) nstg -= NSTG;
                if (ch + 2 < TOTAL) { LOAD_CHUNK(ch + 2, nstg); }
                CP_COMMIT();
            }
            // --- MMAs, streaming A tiles one ahead ---
#pragma unroll
            for (int i = 0; i < 4; i++) {
                if (i < 3) {
                    const int row = wm + (i + 1) * 16 + aRow;
                    const uint32_t ra = bb + row * 128;
                    LDSM4(ahn, ra + SWZC(row, colH + aCol0));
                    if (TERMS == 3) LDSM4(aln, ra + SWZC(row, colH + aCol0 + 64));
                }
#pragma unroll
                for (int j = 0; j < 4; j++) MMA(acc[i][j], ahc, bh[j]);
                if (TERMS == 3) {
#pragma unroll
                    for (int j = 0; j < 4; j++) MMA(acc[i][j], ahc, bl[j]);
#pragma unroll
                    for (int j = 0; j < 4; j++) MMA(acc[i][j], alc, bh[j]);
                }
#pragma unroll
                for (int r = 0; r < 4; r++) {
                    ahc[r] = ahn[r];
                    if (TERMS == 3) alc[r] = aln[r];
                }
            }
        }
        stg = stg + 1; if (stg >= NSTG) stg = 0;
    }
#undef LOAD_CHUNK

    // ---- epilogue (vectorized stores) ----
    const int cr = lane >> 2, cc = (lane & 3) * 2;
#pragma unroll
    for (int i = 0; i < 4; i++) {
        const int r0 = m0 + wm + i * 16 + cr;
#pragma unroll
        for (int j = 0; j < 4; j++) {
            const int col = n0 + wn + j * 8 + cc;
            const size_t o0 = (size_t)z * cBatch + (size_t)r0 * ldC + col;
            const size_t o1 = o0 + (size_t)8 * ldC;
            float v0 = acc[i][j][0] * alpha, v1 = acc[i][j][1] * alpha;
            float v2 = acc[i][j][2] * alpha, v3 = acc[i][j][3] * alpha;
            if (EPI == 0) {
                *(float2*)&Cf[o0] = make_float2(v0, v1);
                *(float2*)&Cf[o1] = make_float2(v2, v3);
            } else {
                float h0 = __half2float(__float2half_rn(v0));
                float h1 = __half2float(__float2half_rn(v1));
                float h2 = __half2float(__float2half_rn(v2));
                float h3 = __half2float(__float2half_rn(v3));
                *(__half2*)&Chi[o0] = __floats2half2_rn(v0, v1);
                *(__half2*)&Chi[o1] = __floats2half2_rn(v2, v3);
                *(__half2*)&Clo[o0] = __floats2half2_rn(v0 - h0, v1 - h1);
                *(__half2*)&Clo[o1] = __floats2half2_rn(v2 - h2, v3 - h3);
            }
        }
    }
}

// ---------------------------------------------------------------------------
// Fused input prep, single launch.
//   z in [0, B_):        x[b] 32x32 tile -> xs (h/r) + xt (h, transposed)
//   z in [B_, B_+H_):    W[h] 32x32 tile -> Wt (h/r, transposed)
// Grid: (D/32, N/32, B_+H_); W-blocks with blockIdx.y >= D/32 exit.
// ---------------------------------------------------------------------------
__global__ __launch_bounds__(256) void split_inputs_kernel(
    const float* __restrict__ x, const float* __restrict__ W)
{
    __shared__ float t[32][33];
    const int z = blockIdx.z;
    const int tx = threadIdx.x & 31, ty = threadIdx.x >> 5;

    if (z < B_) {
        const int b = z;
        const int d0 = blockIdx.x * 32, n0 = blockIdx.y * 32;

        for (int i = ty; i < 32; i += 8)
            t[i][tx] = x[(size_t)b * N_ * D_ + (size_t)(n0 + i) * D_ + d0 + tx];
        __syncthreads();

        for (int i = ty; i < 32; i += 8) {
            float v = t[i][tx];
            __half h = __float2half_rn(v);
            size_t o = (size_t)b * N_ * D_ + (size_t)(n0 + i) * D_ + d0 + tx;
            g_xs_h[o] = h; g_xs_r[o] = __float2half_rn(v - __half2float(h));
        }
        for (int i = ty; i < 32; i += 8) {
            float v = t[tx][i];
            size_t o = (size_t)b * D_ * N_ + (size_t)(d0 + i) * N_ + n0 + tx;
            g_xt_h[o] = __float2half_rn(v);
        }
    } else {
        if (blockIdx.y >= D_ / 32) return;      // W is only D_/32 tiles in y
        const int h = z - B_;
        const int e0 = blockIdx.x * 32, d0 = blockIdx.y * 32;

        for (int i = ty; i < 32; i += 8)
            t[i][tx] = W[(size_t)h * D_ * D_ + (size_t)(d0 + i) * D_ + e0 + tx];
        __syncthreads();

        for (int i = ty; i < 32; i += 8) {
            float v = t[tx][i];   // W[d0+tx][e0+i]
            __half hh = __float2half_rn(v);
            size_t o = (size_t)h * D_ * D_ + (size_t)(e0 + i) * D_ + d0 + tx;
            g_Wt_h[o] = hh; g_Wt_r[o] = __float2half_rn(v - __half2float(hh));
        }
    }
}

// ---------------------------------------------------------------------------
// Softmax: one row per WARP (no smem, no __syncthreads).
// Block = 8 warps = 8 rows; each lane holds 32 elems (8 float4s).
// ---------------------------------------------------------------------------
__global__ __launch_bounds__(256) void softmax_warp_kernel() {
    const int wid = threadIdx.x >> 5, lane = threadIdx.x & 31;
    const size_t row = (size_t)blockIdx.x * 8 + wid;
    const float* p = g_S + row * N_;

    float4 v[8];
    float m = -1e30f;
#pragma unroll
    for (int i = 0; i < 8; i++) {
        v[i] = *(const float4*)&p[(i * 32 + lane) * 4];
        m = fmaxf(m, fmaxf(fmaxf(v[i].x, v[i].y), fmaxf(v[i].z, v[i].w)));
    }
#pragma unroll
    for (int o = 16; o; o >>= 1) m = fmaxf(m, __shfl_xor_sync(0xFFFFFFFFu, m, o));

    float s = 0.f;
#pragma unroll
    for (int i = 0; i < 8; i++) {
        v[i].x = __expf(v[i].x - m); v[i].y = __expf(v[i].y - m);
        v[i].z = __expf(v[i].z - m); v[i].w = __expf(v[i].w - m);
        s += (v[i].x + v[i].y) + (v[i].z + v[i].w);
    }
#pragma unroll
    for (int o = 16; o; o >>= 1) s += __shfl_xor_sync(0xFFFFFFFFu, s, o);
    const float inv = 1.0f / s;

    __half2* dst = (__half2*)&g_P_h[row * N_];
#pragma unroll
    for (int i = 0; i < 8; i++) {
        const int e = (i * 32 + lane) * 2;   // half2 index
        dst[e]     = __floats2half2_rn(v[i].x * inv, v[i].y * inv);
        dst[e + 1] = __floats2half2_rn(v[i].z * inv, v[i].w * inv);
    }
}

// ---------------------------------------------------------------------------
extern "C" void kernel_launch(void* const* d_in, const int* in_sizes, int n_in,
                              void* d_out, int out_size) {
    const float* x = (const float*)d_in[0];   // [8,1024,512]
    const float* W = (const float*)d_in[1];   // [4,512,512]
    float* out = (float*)d_out;               // [8,1024,512]

    cudaFuncSetAttribute(gemm_mma<0, 3, 1>, cudaFuncAttributeMaxDynamicSharedMemorySize, GSMEM);
    cudaFuncSetAttribute(gemm_mma<1, 3, 1>, cudaFuncAttributeMaxDynamicSharedMemorySize, GSMEM);
    cudaFuncSetAttribute(gemm_mma<0, 1, 4>, cudaFuncAttributeMaxDynamicSharedMemorySize, GSMEM);

    __half *xs_h, *xs_r, *xt_h, *Wt_h, *Wt_r, *Y_h, *Y_r, *P_h;
    float* Sf;
    cudaGetSymbolAddress((void**)&xs_h, g_xs_h);
    cudaGetSymbolAddress((void**)&xs_r, g_xs_r);
    cudaGetSymbolAddress((void**)&xt_h, g_xt_h);
    cudaGetSymbolAddress((void**)&Wt_h, g_Wt_h);
    cudaGetSymbolAddress((void**)&Wt_r, g_Wt_r);
    cudaGetSymbolAddress((void**)&Y_h, g_Y_h);
    cudaGetSymbolAddress((void**)&Y_r, g_Y_r);
    cudaGetSymbolAddress((void**)&P_h, g_P_h);
    cudaGetSymbolAddress((void**)&Sf, g_S);

    const float SCALE = 0.04419417382415922f;   // 512^-0.5

    // Fused x/W preprocessing (one launch)
    split_inputs_kernel<<<dim3(D_ / 32, N_ / 32, B_ + H_), 256>>>(x, W);

    // K1: Y[b,h] = xs[b] @ Wt[h]^T  (3-term, NSEG=1) -> fp16 h/r Y
    gemm_mma<1, 3, 1><<<dim3(D_ / 128, N_ / 128, B_ * H_), 256, GSMEM>>>(
        xs_h, xs_r, D_, (size_t)N_ * D_, 4, 8, 0,
        Wt_h, Wt_r, D_, (size_t)D_ * D_, 1, 4,
        nullptr, Y_h, Y_r, D_, (size_t)N_ * D_, 1.0f);

    // K2: S[b,h] = scale * Y[b,h] @ xs[b]^T  (3-term, NSEG=1) -> fp32
    gemm_mma<0, 3, 1><<<dim3(N_ / 128, N_ / 128, B_ * H_), 256, GSMEM>>>(
        Y_h, Y_r, D_, (size_t)N_ * D_, 1, 32, 0,
        xs_h, xs_r, D_, (size_t)N_ * D_, 4, 8,
        Sf, nullptr, nullptr, N_, (size_t)N_ * N_, SCALE);

    softmax_warp_kernel<<<(B_ * H_ * N_) / 8, 256>>>();

    // K4: out[b] = 0.25 * sum_h P_h[b,h] @ xt_h[b]^T  (1-term fp16, NSEG=4)
    gemm_mma<0, 1, 4><<<dim3(D_ / 128, N_ / 128, B_), 256, GSMEM>>>(
        P_h, nullptr, N_, (size_t)H_ * N_ * N_, 1, 8, (size_t)N_ * N_,
        xt_h, nullptr, N_, (size_t)D_ * N_, 1, 8,
        out, nullptr, nullptr, D_, (size_t)N_ * D_, 0.25f);
}